// round 8
// baseline (speedup 1.0000x reference)
#include <cuda_runtime.h>
#include <cuda_bf16.h>
#include <math_constants.h>
#include <cstdint>

// Problem constants
#define B   4
#define S   2048
#define NX  1024
#define H   16
#define D   64
#define M_TOT (B * S)   // 8192

// Scratch
__device__ float g_qkv[(size_t)M_TOT * 3 * NX];   // (8192, 3072)
__device__ float g_ctx[(size_t)M_TOT * NX];       // (8192, 1024) tf32-rounded
__device__ float g_xc[(size_t)M_TOT * NX];        // x, tf32-rounded
__device__ float g_wt1[(size_t)3 * NX * NX];      // c_attn_w^T, tf32, k-interleaved
__device__ float g_wt2[(size_t)NX * NX];          // c_proj_w^T, tf32, k-interleaved
__device__ float g_kc[(size_t)64 * S * D];        // K tf32, [bh][s][d-interleaved]
__device__ float g_vt[(size_t)64 * D * S];        // V tf32, [bh][d][s-interleaved]

// ---------------------------------------------------------------------------
// Helpers
// ---------------------------------------------------------------------------
__device__ __forceinline__ uint32_t f2tf32(float x) {
    uint32_t u;
    asm("cvt.rna.tf32.f32 %0, %1;" : "=r"(u) : "f"(x));
    return u;
}
__device__ __forceinline__ float f2tf32f(float x) {
    return __uint_as_float(f2tf32(x));
}

__device__ __forceinline__ uint32_t smem_u32(const void* p) {
    uint32_t a;
    asm("{ .reg .u64 t; cvta.to.shared.u64 t, %1; cvt.u32.u64 %0, t; }"
        : "=r"(a) : "l"(p));
    return a;
}

#define CP_ASYNC16(dst, src) \
    asm volatile("cp.async.cg.shared.global [%0], [%1], 16;" \
        :: "r"(dst), "l"(src) : "memory")
#define CP_COMMIT() asm volatile("cp.async.commit_group;" ::: "memory")
#define CP_WAIT0()  asm volatile("cp.async.wait_group 0;" ::: "memory")

// mma.sync m16n8k8 tf32: D = A*B + D (fp32 accum)
__device__ __forceinline__ void mma8(float* c, const uint32_t* a,
                                     uint32_t b0, uint32_t b1) {
    asm volatile(
        "mma.sync.aligned.m16n8k8.row.col.f32.tf32.tf32.f32 "
        "{%0,%1,%2,%3}, {%4,%5,%6,%7}, {%8,%9}, {%0,%1,%2,%3};"
        : "+f"(c[0]), "+f"(c[1]), "+f"(c[2]), "+f"(c[3])
        : "r"(a[0]), "r"(a[1]), "r"(a[2]), "r"(a[3]), "r"(b0), "r"(b1));
}

// k-interleave within 16-block: logical r=8a+4c+t -> phys 4t+2a+c
__device__ __forceinline__ int kperm16(int k) {
    const int r = k & 15;
    return (k & ~15) | ((r & 3) << 2) | (((r >> 3) & 1) << 1) | ((r >> 2) & 1);
}
// inverse: phys p -> logical
__device__ __forceinline__ int kinv16(int p) {
    const int r = p & 15;
    return (p & ~15) | (((r >> 1) & 1) << 3) | ((r & 1) << 2) | ((r >> 2) & 3);
}

// ---------------------------------------------------------------------------
// tf32-convert x
// ---------------------------------------------------------------------------
__global__ void cvt_tf32(const float* __restrict__ in, float* __restrict__ out)
{
    const int i = blockIdx.x * 256 + threadIdx.x;
    float4 v = *(const float4*)(in + (size_t)i * 4);
    v.x = f2tf32f(v.x); v.y = f2tf32f(v.y);
    v.z = f2tf32f(v.z); v.w = f2tf32f(v.w);
    *(float4*)(out + (size_t)i * 4) = v;
}

// ---------------------------------------------------------------------------
// Weight transpose + tf32 + k-interleave: Wt[n][kperm16(k)] = tf32(W[k][n])
// ---------------------------------------------------------------------------
__global__ void transpose_cvt(const float* __restrict__ W, float* __restrict__ Wt,
                              int K, int N)
{
    __shared__ float t[32][33];
    const int k0 = blockIdx.y * 32, n0 = blockIdx.x * 32;
    const int x = threadIdx.x, y = threadIdx.y;   // 32 x 8
#pragma unroll
    for (int i = 0; i < 32; i += 8)
        t[y + i][x] = W[(size_t)(k0 + y + i) * N + n0 + x];
    __syncthreads();
#pragma unroll
    for (int i = 0; i < 32; i += 8)
        Wt[(size_t)(n0 + y + i) * K + kperm16(k0 + x)] = f2tf32f(t[x][y + i]);
}

// ---------------------------------------------------------------------------
// Prep K/V: tf32, k-interleave (K: d-axis; V: key-axis), V transpose.
// ---------------------------------------------------------------------------
__global__ __launch_bounds__(256)
void prep_kv(const float* __restrict__ qkv, float* __restrict__ kc,
             float* __restrict__ vt)
{
    __shared__ float vs[64][65];
    const int bh = blockIdx.y;
    const int b = bh >> 4, h = bh & 15;
    const int s0 = blockIdx.x * 64;
    const int tid = threadIdx.x;

    const float* kbase = qkv + (size_t)b * S * (3 * NX) + NX + h * D;
    const float* vbase = qkv + (size_t)b * S * (3 * NX) + 2 * NX + h * D;

    for (int idx = tid; idx < 64 * 16; idx += 256) {
        const int r  = idx >> 4;
        const int ve = idx & 15;
        const size_t grow = (size_t)(s0 + r) * (3 * NX) + ve * 4;
        // K -> kc[bh][s][phys d]; logical d=4ve+j -> phys (16blk)+4j+w, w=ve&3
        float4 kv = *(const float4*)(kbase + grow);
        float* out = kc + ((size_t)bh * S + s0 + r) * D + (ve >> 2) * 16 + (ve & 3);
        out[0]  = f2tf32f(kv.x);
        out[4]  = f2tf32f(kv.y);
        out[8]  = f2tf32f(kv.z);
        out[12] = f2tf32f(kv.w);
        // V -> smem transpose tile vs[d][s]
        float4 vv = *(const float4*)(vbase + grow);
        vs[4 * ve + 0][r] = vv.x;
        vs[4 * ve + 1][r] = vv.y;
        vs[4 * ve + 2][r] = vv.z;
        vs[4 * ve + 3][r] = vv.w;
    }
    __syncthreads();

    for (int idx = tid; idx < 64 * 16; idx += 256) {
        const int d  = idx >> 4;
        const int ve = idx & 15;
        const int pb = ve * 4;
        float4 ov;
        ov.x = f2tf32f(vs[d][kinv16(pb + 0)]);
        ov.y = f2tf32f(vs[d][kinv16(pb + 1)]);
        ov.z = f2tf32f(vs[d][kinv16(pb + 2)]);
        ov.w = f2tf32f(vs[d][kinv16(pb + 3)]);
        *(float4*)(vt + ((size_t)bh * D + d) * S + s0 + pb) = ov;
    }
}

// ---------------------------------------------------------------------------
// tf32 mma GEMM: C[M,N] = A[M,K] @ Bt[N,K]^T + bias[N]
// A: plain tf32. Bt: tf32, k-interleaved. K-tile 64, cp.async staging.
// Block 128x128, 256 threads, warp tile 64x32.
// ---------------------------------------------------------------------------
#define GLD 68

__global__ __launch_bounds__(256)
void gemm_mma(const float* __restrict__ A, const float* __restrict__ Bt,
              const float* __restrict__ bias, float* __restrict__ C,
              int M, int N, int K)
{
    extern __shared__ float gsm[];
    float* As = gsm;                 // [128][GLD]
    float* Bs = gsm + 128 * GLD;     // [128][GLD]
    const uint32_t as_u = smem_u32(As);
    const uint32_t bs_u = smem_u32(Bs);

    const int tid  = threadIdx.x;
    const int wid  = tid >> 5;
    const int lane = tid & 31;
    const int g    = lane >> 2;
    const int tig  = lane & 3;

    const int brow = blockIdx.y * 128;
    const int bcol = blockIdx.x * 128;
    const int wm = (wid >> 2) * 64;
    const int wn = (wid & 3) * 32;

    float c[4][4][4];
#pragma unroll
    for (int mi = 0; mi < 4; mi++)
#pragma unroll
        for (int ni = 0; ni < 4; ni++)
#pragma unroll
            for (int j = 0; j < 4; j++) c[mi][ni][j] = 0.f;

    for (int k0 = 0; k0 < K; k0 += 64) {
        __syncthreads();
#pragma unroll
        for (int i = 0; i < 8; i++) {
            const int v = tid + i * 256;       // 0..2047
            const int r  = v >> 4;             // 0..127
            const int ve = v & 15;
            CP_ASYNC16(as_u + (r * GLD + ve * 4) * 4,
                       A + (size_t)(brow + r) * K + k0 + ve * 4);
            CP_ASYNC16(bs_u + (r * GLD + ve * 4) * 4,
                       Bt + (size_t)(bcol + r) * K + k0 + ve * 4);
        }
        CP_COMMIT();
        CP_WAIT0();
        __syncthreads();

#pragma unroll
        for (int gi = 0; gi < 4; gi++) {
            // B frags for ks pair 2gi, 2gi+1: one LDS.128 per ni
            uint32_t bq[4][4];
#pragma unroll
            for (int ni = 0; ni < 4; ni++) {
                float4 bb = *(const float4*)&Bs[(wn + ni * 8 + g) * GLD + gi * 16 + 4 * tig];
                bq[ni][0] = __float_as_uint(bb.x);
                bq[ni][1] = __float_as_uint(bb.y);
                bq[ni][2] = __float_as_uint(bb.z);
                bq[ni][3] = __float_as_uint(bb.w);
            }
#pragma unroll
            for (int sub = 0; sub < 2; sub++) {
                const int kk = gi * 16 + sub * 8;
                uint32_t af[4][4];
#pragma unroll
                for (int mi = 0; mi < 4; mi++) {
                    const int r = wm + mi * 16;
                    af[mi][0] = __float_as_uint(As[(r + g) * GLD + kk + tig]);
                    af[mi][1] = __float_as_uint(As[(r + g + 8) * GLD + kk + tig]);
                    af[mi][2] = __float_as_uint(As[(r + g) * GLD + kk + tig + 4]);
                    af[mi][3] = __float_as_uint(As[(r + g + 8) * GLD + kk + tig + 4]);
                }
#pragma unroll
                for (int mi = 0; mi < 4; mi++)
#pragma unroll
                    for (int ni = 0; ni < 4; ni++)
                        mma8(c[mi][ni], af[mi], bq[ni][2 * sub], bq[ni][2 * sub + 1]);
            }
        }
    }

#pragma unroll
    for (int mi = 0; mi < 4; mi++) {
        const int row0 = brow + wm + mi * 16 + g;
#pragma unroll
        for (int ni = 0; ni < 4; ni++) {
            const int col = bcol + wn + ni * 8 + 2 * tig;
            float2 bb = *(const float2*)(bias + col);
            float2 v0, v1;
            v0.x = c[mi][ni][0] + bb.x; v0.y = c[mi][ni][1] + bb.y;
            v1.x = c[mi][ni][2] + bb.x; v1.y = c[mi][ni][3] + bb.y;
            *(float2*)(C + (size_t)row0 * N + col) = v0;
            *(float2*)(C + (size_t)(row0 + 8) * N + col) = v1;
        }
    }
}

// ---------------------------------------------------------------------------
// Flash attention with tf32 mma.
// 4 warps, TQ=64, TK=64, 4 CTAs/SM. cp.async staging of pre-converted,
// k-interleaved K/V; B-frags are LDS.128 (2 k-steps each). Ps aliases Q stage.
// ---------------------------------------------------------------------------
#define KP 72
#define PP 68

__global__ void __launch_bounds__(128, 4)
flash_attn_mma(const float* __restrict__ qkv, const float* __restrict__ kc,
               const float* __restrict__ vt, const float* __restrict__ mask,
               float* __restrict__ ctx)
{
    extern __shared__ float sm[];
    float* Ps = sm;                    // [64][PP]  Q staging, then P
    float* Ks = Ps + 64 * PP;          // [64][KP]  (key, d phys-interleaved)
    float* Vt = Ks + 64 * KP;          // [64][KP]  (d, key phys-interleaved)
    float* mk = Vt + 64 * KP;          // [64]
    const uint32_t ks_u = smem_u32(Ks);
    const uint32_t vt_u = smem_u32(Vt);
    const uint32_t mk_u = smem_u32(mk);

    const int bh = blockIdx.y;
    const int b  = bh >> 4;
    const int h  = bh & 15;
    const int q0 = blockIdx.x * 64;

    const int tid  = threadIdx.x;
    const int wid  = tid >> 5;
    const int lane = tid & 31;
    const int g    = lane >> 2;
    const int tig  = lane & 3;
    const int m0   = wid * 16;

    // Stage Q (tf32) into Ps region, hoist fragments (logical layout)
    const float* qptr = qkv + (size_t)b * S * (3 * NX) + (size_t)h * D;
    for (int idx = tid; idx < 64 * 16; idx += 128) {
        const int r  = idx >> 4;
        const int ve = idx & 15;
        float4 qa = *(const float4*)(qptr + (size_t)(q0 + r) * (3 * NX) + ve * 4);
        float* dst = &Ps[r * PP + ve * 4];
        dst[0] = f2tf32f(qa.x);
        dst[1] = f2tf32f(qa.y);
        dst[2] = f2tf32f(qa.z);
        dst[3] = f2tf32f(qa.w);
    }
    __syncthreads();

    uint32_t aq[8][4];
#pragma unroll
    for (int ks = 0; ks < 8; ks++) {
        const int kk = ks * 8;
        aq[ks][0] = __float_as_uint(Ps[(m0 + g) * PP + kk + tig]);
        aq[ks][1] = __float_as_uint(Ps[(m0 + g + 8) * PP + kk + tig]);
        aq[ks][2] = __float_as_uint(Ps[(m0 + g) * PP + kk + tig + 4]);
        aq[ks][3] = __float_as_uint(Ps[(m0 + g + 8) * PP + kk + tig + 4]);
    }

    float mi0 = -CUDART_INF_F, mi1 = -CUDART_INF_F;
    float li0 = 0.f, li1 = 0.f;
    float o[8][4];
#pragma unroll
    for (int ni = 0; ni < 8; ni++)
#pragma unroll
        for (int j = 0; j < 4; j++) o[ni][j] = 0.f;

    const float* kcb = kc + (size_t)bh * S * D;
    const float* vtb = vt + (size_t)bh * D * S;
    const float* mkb = mask + (size_t)b * S;

    for (int kt = 0; kt < S / 64; kt++) {
        const int k0g = kt * 64;
        __syncthreads();   // previous iteration's reads complete

        // cp.async staging of K/V tiles + mask
        for (int idx = tid; idx < 64 * 16; idx += 128) {
            const int r  = idx >> 4;
            const int ve = idx & 15;
            CP_ASYNC16(ks_u + (r * KP + ve * 4) * 4,
                       kcb + (size_t)(k0g + r) * D + ve * 4);
            CP_ASYNC16(vt_u + (r * KP + ve * 4) * 4,
                       vtb + (size_t)r * S + k0g + ve * 4);
        }
        if (tid < 16)
            CP_ASYNC16(mk_u + tid * 16, mkb + k0g + tid * 4);
        CP_COMMIT();
        CP_WAIT0();
        __syncthreads();

        // ---- QK^T : B-frags as LDS.128 (2 ks per load)
        float c[8][4];
#pragma unroll
        for (int ni = 0; ni < 8; ni++)
#pragma unroll
            for (int j = 0; j < 4; j++) c[ni][j] = 0.f;

#pragma unroll
        for (int gi = 0; gi < 4; gi++) {
#pragma unroll
            for (int hf = 0; hf < 2; hf++) {
                uint32_t bq[4][4];
#pragma unroll
                for (int n4 = 0; n4 < 4; n4++) {
                    const int ni = hf * 4 + n4;
                    float4 bb = *(const float4*)&Ks[(ni * 8 + g) * KP + gi * 16 + 4 * tig];
                    bq[n4][0] = __float_as_uint(bb.x);
                    bq[n4][1] = __float_as_uint(bb.y);
                    bq[n4][2] = __float_as_uint(bb.z);
                    bq[n4][3] = __float_as_uint(bb.w);
                }
#pragma unroll
                for (int sub = 0; sub < 2; sub++)
#pragma unroll
                    for (int n4 = 0; n4 < 4; n4++)
                        mma8(c[hf * 4 + n4], aq[2 * gi + sub],
                             bq[n4][2 * sub], bq[n4][2 * sub + 1]);
            }
        }

        // ---- scale + mask
#pragma unroll
        for (int ni = 0; ni < 8; ni++) {
            float2 mm = *(const float2*)&mk[ni * 8 + 2 * tig];
            c[ni][0] = fmaf(c[ni][0], 0.125f, mm.x);
            c[ni][1] = fmaf(c[ni][1], 0.125f, mm.y);
            c[ni][2] = fmaf(c[ni][2], 0.125f, mm.x);
            c[ni][3] = fmaf(c[ni][3], 0.125f, mm.y);
        }

        // ---- online softmax
        float mt0 = -CUDART_INF_F, mt1 = -CUDART_INF_F;
#pragma unroll
        for (int ni = 0; ni < 8; ni++) {
            mt0 = fmaxf(mt0, fmaxf(c[ni][0], c[ni][1]));
            mt1 = fmaxf(mt1, fmaxf(c[ni][2], c[ni][3]));
        }
        mt0 = fmaxf(mt0, __shfl_xor_sync(0xffffffffu, mt0, 1));
        mt0 = fmaxf(mt0, __shfl_xor_sync(0xffffffffu, mt0, 2));
        mt1 = fmaxf(mt1, __shfl_xor_sync(0xffffffffu, mt1, 1));
        mt1 = fmaxf(mt1, __shfl_xor_sync(0xffffffffu, mt1, 2));

        const float mn0 = fmaxf(mi0, mt0);
        const float mn1 = fmaxf(mi1, mt1);
        const float fac0 = __expf(mi0 - mn0);
        const float fac1 = __expf(mi1 - mn1);
        mi0 = mn0; mi1 = mn1;

        float lt0 = 0.f, lt1 = 0.f;
#pragma unroll
        for (int ni = 0; ni < 8; ni++) {
            c[ni][0] = __expf(c[ni][0] - mn0);
            c[ni][1] = __expf(c[ni][1] - mn0);
            c[ni][2] = __expf(c[ni][2] - mn1);
            c[ni][3] = __expf(c[ni][3] - mn1);
            lt0 += c[ni][0] + c[ni][1];
            lt1 += c[ni][2] + c[ni][3];
        }
        lt0 += __shfl_xor_sync(0xffffffffu, lt0, 1);
        lt0 += __shfl_xor_sync(0xffffffffu, lt0, 2);
        lt1 += __shfl_xor_sync(0xffffffffu, lt1, 1);
        lt1 += __shfl_xor_sync(0xffffffffu, lt1, 2);
        li0 = li0 * fac0 + lt0;
        li1 = li1 * fac1 + lt1;

#pragma unroll
        for (int ni = 0; ni < 8; ni++) {
            o[ni][0] *= fac0; o[ni][1] *= fac0;
            o[ni][2] *= fac1; o[ni][3] *= fac1;
        }

        // ---- store P (tf32, logical key layout) to own rows
#pragma unroll
        for (int ni = 0; ni < 8; ni++) {
            const int jc = ni * 8 + 2 * tig;
            float2 p0, p1;
            p0.x = f2tf32f(c[ni][0]);
            p0.y = f2tf32f(c[ni][1]);
            p1.x = f2tf32f(c[ni][2]);
            p1.y = f2tf32f(c[ni][3]);
            *(float2*)&Ps[(m0 + g) * PP + jc]     = p0;
            *(float2*)&Ps[(m0 + g + 8) * PP + jc] = p1;
        }
        __syncwarp();

        // ---- O += P @ V : B-frags as LDS.128 (2 ks per load)
#pragma unroll
        for (int gi = 0; gi < 4; gi++) {
            uint32_t ap2[2][4];
#pragma unroll
            for (int sub = 0; sub < 2; sub++) {
                const int kk = (2 * gi + sub) * 8;
                ap2[sub][0] = __float_as_uint(Ps[(m0 + g) * PP + kk + tig]);
                ap2[sub][1] = __float_as_uint(Ps[(m0 + g + 8) * PP + kk + tig]);
                ap2[sub][2] = __float_as_uint(Ps[(m0 + g) * PP + kk + tig + 4]);
                ap2[sub][3] = __float_as_uint(Ps[(m0 + g + 8) * PP + kk + tig + 4]);
            }
#pragma unroll
            for (int hf = 0; hf < 2; hf++) {
                uint32_t bq[4][4];
#pragma unroll
                for (int n4 = 0; n4 < 4; n4++) {
                    const int ni = hf * 4 + n4;
                    float4 bb = *(const float4*)&Vt[(ni * 8 + g) * KP + gi * 16 + 4 * tig];
                    bq[n4][0] = __float_as_uint(bb.x);
                    bq[n4][1] = __float_as_uint(bb.y);
                    bq[n4][2] = __float_as_uint(bb.z);
                    bq[n4][3] = __float_as_uint(bb.w);
                }
#pragma unroll
                for (int sub = 0; sub < 2; sub++)
#pragma unroll
                    for (int n4 = 0; n4 < 4; n4++)
                        mma8(o[hf * 4 + n4], ap2[sub],
                             bq[n4][2 * sub], bq[n4][2 * sub + 1]);
            }
        }
    }

    // ---- normalize + write merged-heads context (tf32-rounded for proj GEMM)
    const float inv0 = 1.f / li0;
    const float inv1 = 1.f / li1;
    const size_t row0 = (size_t)b * S + q0 + m0 + g;
#pragma unroll
    for (int ni = 0; ni < 8; ni++) {
        const int col = h * D + ni * 8 + 2 * tig;
        float2 v0, v1;
        v0.x = f2tf32f(o[ni][0] * inv0); v0.y = f2tf32f(o[ni][1] * inv0);
        v1.x = f2tf32f(o[ni][2] * inv1); v1.y = f2tf32f(o[ni][3] * inv1);
        *(float2*)(ctx + row0 * NX + col)       = v0;
        *(float2*)(ctx + (row0 + 8) * NX + col) = v1;
    }
}

// ---------------------------------------------------------------------------
// Launch
// ---------------------------------------------------------------------------
extern "C" void kernel_launch(void* const* d_in, const int* in_sizes, int n_in,
                              void* d_out, int out_size)
{
    const float* x        = (const float*)d_in[0];
    const float* mask     = (const float*)d_in[1];
    const float* c_attn_w = (const float*)d_in[2];
    const float* c_attn_b = (const float*)d_in[3];
    const float* c_proj_w = (const float*)d_in[4];
    const float* c_proj_b = (const float*)d_in[5];
    float* out = (float*)d_out;

    float *qkv, *ctx, *xc, *wt1, *wt2, *kc, *vt;
    cudaGetSymbolAddress((void**)&qkv, g_qkv);
    cudaGetSymbolAddress((void**)&ctx, g_ctx);
    cudaGetSymbolAddress((void**)&xc,  g_xc);
    cudaGetSymbolAddress((void**)&wt1, g_wt1);
    cudaGetSymbolAddress((void**)&wt2, g_wt2);
    cudaGetSymbolAddress((void**)&kc,  g_kc);
    cudaGetSymbolAddress((void**)&vt,  g_vt);

    // 0) Pre-convert / pre-permute
    cvt_tf32<<<M_TOT * NX / (256 * 4), 256>>>(x, xc);
    transpose_cvt<<<dim3(3 * NX / 32, NX / 32), dim3(32, 8)>>>(c_attn_w, wt1, NX, 3 * NX);
    transpose_cvt<<<dim3(NX / 32, NX / 32),     dim3(32, 8)>>>(c_proj_w, wt2, NX, NX);

    const int gsm_bytes = 2 * 128 * GLD * (int)sizeof(float);   // 69632
    cudaFuncSetAttribute(gemm_mma, cudaFuncAttributeMaxDynamicSharedMemorySize, gsm_bytes);

    // 1) QKV projection
    gemm_mma<<<dim3(3 * NX / 128, M_TOT / 128), 256, gsm_bytes>>>(
        xc, wt1, c_attn_b, qkv, M_TOT, 3 * NX, NX);

    // 1.5) Prep K/V
    prep_kv<<<dim3(S / 64, 64), 256>>>(qkv, kc, vt);

    // 2) Flash attention
    {
        const int smem = (64 * PP + 2 * 64 * KP + 64) * (int)sizeof(float); // 54528
        cudaFuncSetAttribute(flash_attn_mma, cudaFuncAttributeMaxDynamicSharedMemorySize, smem);
        dim3 grid(S / 64, B * H);
        flash_attn_mma<<<grid, 128, smem>>>(qkv, kc, vt, mask, ctx);
    }

    // 3) Output projection
    gemm_mma<<<dim3(NX / 128, M_TOT / 128), 256, gsm_bytes>>>(
        ctx, wt2, c_proj_b, out, M_TOT, NX, NX);
}

// round 9
// speedup vs baseline: 1.0103x; 1.0103x over previous
#include <cuda_runtime.h>
#include <cuda_bf16.h>
#include <math_constants.h>
#include <cstdint>

// Problem constants
#define B   4
#define S   2048
#define NX  1024
#define H   16
#define D   64
#define M_TOT (B * S)   // 8192

// Scratch
__device__ float g_qkv[(size_t)M_TOT * 3 * NX];   // (8192, 3072)
__device__ float g_ctx[(size_t)M_TOT * NX];       // (8192, 1024) tf32-rounded
__device__ float g_xc[(size_t)M_TOT * NX];        // x, tf32-rounded
__device__ float g_wt1[(size_t)3 * NX * NX];      // c_attn_w^T, tf32
__device__ float g_wt2[(size_t)NX * NX];          // c_proj_w^T, tf32
__device__ float g_kc[(size_t)64 * S * D];        // K tf32, [bh][s][d-pperm]
__device__ float g_vt[(size_t)64 * D * S];        // V tf32, [bh][d][s-pperm]

// ---------------------------------------------------------------------------
// Helpers
// ---------------------------------------------------------------------------
__device__ __forceinline__ uint32_t f2tf32(float x) {
    uint32_t u;
    asm("cvt.rna.tf32.f32 %0, %1;" : "=r"(u) : "f"(x));
    return u;
}
__device__ __forceinline__ float f2tf32f(float x) {
    return __uint_as_float(f2tf32(x));
}

__device__ __forceinline__ uint32_t smem_u32(const void* p) {
    uint32_t a;
    asm("{ .reg .u64 t; cvta.to.shared.u64 t, %1; cvt.u32.u64 %0, t; }"
        : "=r"(a) : "l"(p));
    return a;
}

#define CP_ASYNC16(dst, src) \
    asm volatile("cp.async.cg.shared.global [%0], [%1], 16;" \
        :: "r"(dst), "l"(src) : "memory")
#define CP_COMMIT() asm volatile("cp.async.commit_group;" ::: "memory")
#define CP_WAIT(n)  asm volatile("cp.async.wait_group %0;" :: "n"(n) : "memory")

// mma.sync m16n8k8 tf32: D = A*B + D (fp32 accum)
__device__ __forceinline__ void mma8(float* c, const uint32_t* a,
                                     uint32_t b0, uint32_t b1) {
    asm volatile(
        "mma.sync.aligned.m16n8k8.row.col.f32.tf32.tf32.f32 "
        "{%0,%1,%2,%3}, {%4,%5,%6,%7}, {%8,%9}, {%0,%1,%2,%3};"
        : "+f"(c[0]), "+f"(c[1]), "+f"(c[2]), "+f"(c[3])
        : "r"(a[0]), "r"(a[1]), "r"(a[2]), "r"(a[3]), "r"(b0), "r"(b1));
}

// inverse of pair-permutation e -> 2*(e&3) + ((e>>2)&1)
__device__ __forceinline__ int pinv(int p) {
    return (p & ~7) | (((p & 7) >> 1) + 4 * (p & 1));
}

// ---------------------------------------------------------------------------
// tf32-convert x
// ---------------------------------------------------------------------------
__global__ void cvt_tf32(const float* __restrict__ in, float* __restrict__ out)
{
    const int i = blockIdx.x * 256 + threadIdx.x;
    float4 v = *(const float4*)(in + (size_t)i * 4);
    v.x = f2tf32f(v.x); v.y = f2tf32f(v.y);
    v.z = f2tf32f(v.z); v.w = f2tf32f(v.w);
    *(float4*)(out + (size_t)i * 4) = v;
}

// ---------------------------------------------------------------------------
// Weight transpose + tf32 convert: Wt[n][k] = tf32(W[k][n])
// ---------------------------------------------------------------------------
__global__ void transpose_cvt(const float* __restrict__ W, float* __restrict__ Wt,
                              int K, int N)
{
    __shared__ float t[32][33];
    const int k0 = blockIdx.y * 32, n0 = blockIdx.x * 32;
    const int x = threadIdx.x, y = threadIdx.y;   // 32 x 8
#pragma unroll
    for (int i = 0; i < 32; i += 8)
        t[y + i][x] = W[(size_t)(k0 + y + i) * N + n0 + x];
    __syncthreads();
#pragma unroll
    for (int i = 0; i < 32; i += 8)
        Wt[(size_t)(n0 + y + i) * K + k0 + x] = f2tf32f(t[x][y + i]);
}

// ---------------------------------------------------------------------------
// Prep K/V (round-7): tf32, pair-permute, V transpose.
// ---------------------------------------------------------------------------
__global__ __launch_bounds__(256)
void prep_kv(const float* __restrict__ qkv, float* __restrict__ kc,
             float* __restrict__ vt)
{
    __shared__ float vs[64][65];
    const int bh = blockIdx.y;
    const int b = bh >> 4, h = bh & 15;
    const int s0 = blockIdx.x * 64;
    const int tid = threadIdx.x;

    const float* kbase = qkv + (size_t)b * S * (3 * NX) + NX + h * D;
    const float* vbase = qkv + (size_t)b * S * (3 * NX) + 2 * NX + h * D;

    for (int idx = tid; idx < 64 * 16; idx += 256) {
        const int r  = idx >> 4;
        const int ve = idx & 15;
        const size_t grow = (size_t)(s0 + r) * (3 * NX) + ve * 4;
        float4 kv = *(const float4*)(kbase + grow);
        float* out = kc + ((size_t)bh * S + s0 + r) * D + (ve >> 1) * 8 + (ve & 1);
        out[0] = f2tf32f(kv.x);
        out[2] = f2tf32f(kv.y);
        out[4] = f2tf32f(kv.z);
        out[6] = f2tf32f(kv.w);
        float4 vv = *(const float4*)(vbase + grow);
        vs[4 * ve + 0][r] = vv.x;
        vs[4 * ve + 1][r] = vv.y;
        vs[4 * ve + 2][r] = vv.z;
        vs[4 * ve + 3][r] = vv.w;
    }
    __syncthreads();

    for (int idx = tid; idx < 64 * 16; idx += 256) {
        const int d  = idx >> 4;
        const int ve = idx & 15;
        const int pb = ve * 4;
        float4 ov;
        ov.x = f2tf32f(vs[d][pinv(pb + 0)]);
        ov.y = f2tf32f(vs[d][pinv(pb + 1)]);
        ov.z = f2tf32f(vs[d][pinv(pb + 2)]);
        ov.w = f2tf32f(vs[d][pinv(pb + 3)]);
        *(float4*)(vt + ((size_t)bh * D + d) * S + s0 + pb) = ov;
    }
}

// ---------------------------------------------------------------------------
// tf32 mma GEMM, 2-stage cp.async pipeline:
// C[M,N] = A[M,K] @ Bt[N,K]^T + bias[N]
// Block 128x128, K-tile 32, 256 threads, warp tile 64x32, 2 CTAs/SM.
// ---------------------------------------------------------------------------
#define GLD 36

__global__ void __launch_bounds__(256, 2)
gemm_mma(const float* __restrict__ A, const float* __restrict__ Bt,
         const float* __restrict__ bias, float* __restrict__ C,
         int M, int N, int K)
{
    extern __shared__ float gsm[];
    // [2 buffers][A|B][128][GLD]
    float* As[2] = {gsm,               gsm + 2 * 128 * GLD};
    float* Bs[2] = {gsm + 128 * GLD,   gsm + 3 * 128 * GLD};

    const int tid  = threadIdx.x;
    const int wid  = tid >> 5;
    const int lane = tid & 31;
    const int g    = lane >> 2;
    const int tig  = lane & 3;

    const int brow = blockIdx.y * 128;
    const int bcol = blockIdx.x * 128;
    const int wm = (wid >> 2) * 64;
    const int wn = (wid & 3) * 32;

    // Per-thread load slots: 4 float4 per matrix per tile
    const int lr  = tid >> 1;            // row 0..127
    const int lv  = (tid & 1) * 4;       // float4 col 0 or 4 -> words lv*4
    // covers ve = lv, lv+1, lv+2, lv+3

    float c[4][4][4];
#pragma unroll
    for (int mi = 0; mi < 4; mi++)
#pragma unroll
        for (int ni = 0; ni < 4; ni++)
#pragma unroll
            for (int j = 0; j < 4; j++) c[mi][ni][j] = 0.f;

    const int KT = K / 32;

    // Issue tile 0
    {
        const uint32_t au = smem_u32(As[0]);
        const uint32_t bu = smem_u32(Bs[0]);
#pragma unroll
        for (int i = 0; i < 4; i++) {
            const int ve = lv + i;
            CP_ASYNC16(au + (lr * GLD + ve * 4) * 4,
                       A + (size_t)(brow + lr) * K + ve * 4);
            CP_ASYNC16(bu + (lr * GLD + ve * 4) * 4,
                       Bt + (size_t)(bcol + lr) * K + ve * 4);
        }
        CP_COMMIT();
    }

    for (int kc = 0; kc < KT; kc++) {
        // Prefetch next tile into the other buffer
        if (kc + 1 < KT) {
            const int nb = (kc + 1) & 1;
            const int k0 = (kc + 1) * 32;
            const uint32_t au = smem_u32(As[nb]);
            const uint32_t bu = smem_u32(Bs[nb]);
#pragma unroll
            for (int i = 0; i < 4; i++) {
                const int ve = lv + i;
                CP_ASYNC16(au + (lr * GLD + ve * 4) * 4,
                           A + (size_t)(brow + lr) * K + k0 + ve * 4);
                CP_ASYNC16(bu + (lr * GLD + ve * 4) * 4,
                           Bt + (size_t)(bcol + lr) * K + k0 + ve * 4);
            }
            CP_COMMIT();
            CP_WAIT(1);        // current tile complete, next may be in flight
        } else {
            CP_WAIT(0);
        }
        __syncthreads();

        const float* Ab = As[kc & 1];
        const float* Bb = Bs[kc & 1];

#pragma unroll
        for (int ks = 0; ks < 4; ks++) {
            const int kk = ks * 8;
            uint32_t af[4][4], bf[4][2];
#pragma unroll
            for (int mi = 0; mi < 4; mi++) {
                const int r = wm + mi * 16;
                af[mi][0] = __float_as_uint(Ab[(r + g) * GLD + kk + tig]);
                af[mi][1] = __float_as_uint(Ab[(r + g + 8) * GLD + kk + tig]);
                af[mi][2] = __float_as_uint(Ab[(r + g) * GLD + kk + tig + 4]);
                af[mi][3] = __float_as_uint(Ab[(r + g + 8) * GLD + kk + tig + 4]);
            }
#pragma unroll
            for (int ni = 0; ni < 4; ni++) {
                const int r = wn + ni * 8;
                bf[ni][0] = __float_as_uint(Bb[(r + g) * GLD + kk + tig]);
                bf[ni][1] = __float_as_uint(Bb[(r + g) * GLD + kk + tig + 4]);
            }
#pragma unroll
            for (int mi = 0; mi < 4; mi++)
#pragma unroll
                for (int ni = 0; ni < 4; ni++)
                    mma8(c[mi][ni], af[mi], bf[ni][0], bf[ni][1]);
        }
        __syncthreads();   // done reading this buffer before it is re-filled
    }

#pragma unroll
    for (int mi = 0; mi < 4; mi++) {
        const int row0 = brow + wm + mi * 16 + g;
#pragma unroll
        for (int ni = 0; ni < 4; ni++) {
            const int col = bcol + wn + ni * 8 + 2 * tig;
            float2 bb = *(const float2*)(bias + col);
            float2 v0, v1;
            v0.x = c[mi][ni][0] + bb.x; v0.y = c[mi][ni][1] + bb.y;
            v1.x = c[mi][ni][2] + bb.x; v1.y = c[mi][ni][3] + bb.y;
            *(float2*)(C + (size_t)row0 * N + col) = v0;
            *(float2*)(C + (size_t)(row0 + 8) * N + col) = v1;
        }
    }
}

// ---------------------------------------------------------------------------
// Flash attention (round-7, proven): 4 warps, TQ=64, TK=64, 4 CTAs/SM.
// Copy-only staging from pre-permuted g_kc/g_vt; LDS.64 B-frags at stride 72.
// ---------------------------------------------------------------------------
#define KP 72
#define PP 68

__global__ void __launch_bounds__(128, 4)
flash_attn_mma(const float* __restrict__ qkv, const float* __restrict__ kc,
               const float* __restrict__ vt, const float* __restrict__ mask,
               float* __restrict__ ctx)
{
    extern __shared__ float sm[];
    float* Ps = sm;                    // [64][PP]  Q staging, then P
    float* Ks = Ps + 64 * PP;          // [64][KP]
    float* Vt = Ks + 64 * KP;          // [64][KP]
    float* mk = Vt + 64 * KP;          // [64]

    const int bh = blockIdx.y;
    const int b  = bh >> 4;
    const int h  = bh & 15;
    const int q0 = blockIdx.x * 64;

    const int tid  = threadIdx.x;
    const int wid  = tid >> 5;
    const int lane = tid & 31;
    const int g    = lane >> 2;
    const int tig  = lane & 3;
    const int m0   = wid * 16;

    const float* qptr = qkv + (size_t)b * S * (3 * NX) + (size_t)h * D;
    for (int idx = tid; idx < 64 * 16; idx += 128) {
        const int r  = idx >> 4;
        const int ve = idx & 15;
        float4 qa = *(const float4*)(qptr + (size_t)(q0 + r) * (3 * NX) + ve * 4);
        float* dst = &Ps[r * PP + ve * 4];
        dst[0] = f2tf32f(qa.x);
        dst[1] = f2tf32f(qa.y);
        dst[2] = f2tf32f(qa.z);
        dst[3] = f2tf32f(qa.w);
    }
    __syncthreads();

    uint32_t aq[8][4];
#pragma unroll
    for (int ks = 0; ks < 8; ks++) {
        const int kk = ks * 8;
        aq[ks][0] = __float_as_uint(Ps[(m0 + g) * PP + kk + tig]);
        aq[ks][1] = __float_as_uint(Ps[(m0 + g + 8) * PP + kk + tig]);
        aq[ks][2] = __float_as_uint(Ps[(m0 + g) * PP + kk + tig + 4]);
        aq[ks][3] = __float_as_uint(Ps[(m0 + g + 8) * PP + kk + tig + 4]);
    }

    float mi0 = -CUDART_INF_F, mi1 = -CUDART_INF_F;
    float li0 = 0.f, li1 = 0.f;
    float o[8][4];
#pragma unroll
    for (int ni = 0; ni < 8; ni++)
#pragma unroll
        for (int j = 0; j < 4; j++) o[ni][j] = 0.f;

    const float* kcb = kc + (size_t)bh * S * D;
    const float* vtb = vt + (size_t)bh * D * S;

    for (int kt = 0; kt < S / 64; kt++) {
        const int k0g = kt * 64;
        __syncthreads();

        for (int idx = tid; idx < 64 * 16; idx += 128) {
            const int r  = idx >> 4;
            const int ve = idx & 15;
            float4 kv = *(const float4*)(kcb + (size_t)(k0g + r) * D + ve * 4);
            *(float4*)&Ks[r * KP + ve * 4] = kv;
            float4 vv = *(const float4*)(vtb + (size_t)r * S + k0g + ve * 4);
            *(float4*)&Vt[r * KP + ve * 4] = vv;
        }
        if (tid < 16)
            *(float4*)&mk[tid * 4] = *(const float4*)&mask[(size_t)b * S + k0g + tid * 4];
        __syncthreads();

        // ---- QK^T
        float c[8][4];
#pragma unroll
        for (int ni = 0; ni < 8; ni++)
#pragma unroll
            for (int j = 0; j < 4; j++) c[ni][j] = 0.f;

#pragma unroll
        for (int ks = 0; ks < 8; ks++) {
            const int kk = ks * 8 + 2 * tig;
            uint32_t bf[8][2];
#pragma unroll
            for (int ni = 0; ni < 8; ni++) {
                float2 bb = *(const float2*)&Ks[(ni * 8 + g) * KP + kk];
                bf[ni][0] = __float_as_uint(bb.x);
                bf[ni][1] = __float_as_uint(bb.y);
            }
#pragma unroll
            for (int ni = 0; ni < 8; ni++)
                mma8(c[ni], aq[ks], bf[ni][0], bf[ni][1]);
        }

        // ---- scale + mask
#pragma unroll
        for (int ni = 0; ni < 8; ni++) {
            float2 mm = *(const float2*)&mk[ni * 8 + 2 * tig];
            c[ni][0] = fmaf(c[ni][0], 0.125f, mm.x);
            c[ni][1] = fmaf(c[ni][1], 0.125f, mm.y);
            c[ni][2] = fmaf(c[ni][2], 0.125f, mm.x);
            c[ni][3] = fmaf(c[ni][3], 0.125f, mm.y);
        }

        // ---- online softmax
        float mt0 = -CUDART_INF_F, mt1 = -CUDART_INF_F;
#pragma unroll
        for (int ni = 0; ni < 8; ni++) {
            mt0 = fmaxf(mt0, fmaxf(c[ni][0], c[ni][1]));
            mt1 = fmaxf(mt1, fmaxf(c[ni][2], c[ni][3]));
        }
        mt0 = fmaxf(mt0, __shfl_xor_sync(0xffffffffu, mt0, 1));
        mt0 = fmaxf(mt0, __shfl_xor_sync(0xffffffffu, mt0, 2));
        mt1 = fmaxf(mt1, __shfl_xor_sync(0xffffffffu, mt1, 1));
        mt1 = fmaxf(mt1, __shfl_xor_sync(0xffffffffu, mt1, 2));

        const float mn0 = fmaxf(mi0, mt0);
        const float mn1 = fmaxf(mi1, mt1);
        const float fac0 = __expf(mi0 - mn0);
        const float fac1 = __expf(mi1 - mn1);
        mi0 = mn0; mi1 = mn1;

        float lt0 = 0.f, lt1 = 0.f;
#pragma unroll
        for (int ni = 0; ni < 8; ni++) {
            c[ni][0] = __expf(c[ni][0] - mn0);
            c[ni][1] = __expf(c[ni][1] - mn0);
            c[ni][2] = __expf(c[ni][2] - mn1);
            c[ni][3] = __expf(c[ni][3] - mn1);
            lt0 += c[ni][0] + c[ni][1];
            lt1 += c[ni][2] + c[ni][3];
        }
        lt0 += __shfl_xor_sync(0xffffffffu, lt0, 1);
        lt0 += __shfl_xor_sync(0xffffffffu, lt0, 2);
        lt1 += __shfl_xor_sync(0xffffffffu, lt1, 1);
        lt1 += __shfl_xor_sync(0xffffffffu, lt1, 2);
        li0 = li0 * fac0 + lt0;
        li1 = li1 * fac1 + lt1;

#pragma unroll
        for (int ni = 0; ni < 8; ni++) {
            o[ni][0] *= fac0; o[ni][1] *= fac0;
            o[ni][2] *= fac1; o[ni][3] *= fac1;
        }

        // ---- store P (tf32) to own rows
#pragma unroll
        for (int ni = 0; ni < 8; ni++) {
            const int jc = ni * 8 + 2 * tig;
            float2 p0, p1;
            p0.x = f2tf32f(c[ni][0]);
            p0.y = f2tf32f(c[ni][1]);
            p1.x = f2tf32f(c[ni][2]);
            p1.y = f2tf32f(c[ni][3]);
            *(float2*)&Ps[(m0 + g) * PP + jc]     = p0;
            *(float2*)&Ps[(m0 + g + 8) * PP + jc] = p1;
        }
        __syncwarp();

        // ---- O += P @ V
#pragma unroll
        for (int ks = 0; ks < 8; ks++) {
            const int kk = ks * 8;
            uint32_t ap[4];
            ap[0] = __float_as_uint(Ps[(m0 + g) * PP + kk + tig]);
            ap[1] = __float_as_uint(Ps[(m0 + g + 8) * PP + kk + tig]);
            ap[2] = __float_as_uint(Ps[(m0 + g) * PP + kk + tig + 4]);
            ap[3] = __float_as_uint(Ps[(m0 + g + 8) * PP + kk + tig + 4]);
            const int kkp = kk + 2 * tig;
            uint32_t bf[8][2];
#pragma unroll
            for (int ni = 0; ni < 8; ni++) {
                float2 bb = *(const float2*)&Vt[(ni * 8 + g) * KP + kkp];
                bf[ni][0] = __float_as_uint(bb.x);
                bf[ni][1] = __float_as_uint(bb.y);
            }
#pragma unroll
            for (int ni = 0; ni < 8; ni++)
                mma8(o[ni], ap, bf[ni][0], bf[ni][1]);
        }
    }

    // ---- normalize + write merged-heads context (tf32-rounded)
    const float inv0 = 1.f / li0;
    const float inv1 = 1.f / li1;
    const size_t row0 = (size_t)b * S + q0 + m0 + g;
#pragma unroll
    for (int ni = 0; ni < 8; ni++) {
        const int col = h * D + ni * 8 + 2 * tig;
        float2 v0, v1;
        v0.x = f2tf32f(o[ni][0] * inv0); v0.y = f2tf32f(o[ni][1] * inv0);
        v1.x = f2tf32f(o[ni][2] * inv1); v1.y = f2tf32f(o[ni][3] * inv1);
        *(float2*)(ctx + row0 * NX + col)       = v0;
        *(float2*)(ctx + (row0 + 8) * NX + col) = v1;
    }
}

// ---------------------------------------------------------------------------
// Launch
// ---------------------------------------------------------------------------
extern "C" void kernel_launch(void* const* d_in, const int* in_sizes, int n_in,
                              void* d_out, int out_size)
{
    const float* x        = (const float*)d_in[0];
    const float* mask     = (const float*)d_in[1];
    const float* c_attn_w = (const float*)d_in[2];
    const float* c_attn_b = (const float*)d_in[3];
    const float* c_proj_w = (const float*)d_in[4];
    const float* c_proj_b = (const float*)d_in[5];
    float* out = (float*)d_out;

    float *qkv, *ctx, *xc, *wt1, *wt2, *kc, *vt;
    cudaGetSymbolAddress((void**)&qkv, g_qkv);
    cudaGetSymbolAddress((void**)&ctx, g_ctx);
    cudaGetSymbolAddress((void**)&xc,  g_xc);
    cudaGetSymbolAddress((void**)&wt1, g_wt1);
    cudaGetSymbolAddress((void**)&wt2, g_wt2);
    cudaGetSymbolAddress((void**)&kc,  g_kc);
    cudaGetSymbolAddress((void**)&vt,  g_vt);

    // 0) Pre-convert / pre-transpose
    cvt_tf32<<<M_TOT * NX / (256 * 4), 256>>>(x, xc);
    transpose_cvt<<<dim3(3 * NX / 32, NX / 32), dim3(32, 8)>>>(c_attn_w, wt1, NX, 3 * NX);
    transpose_cvt<<<dim3(NX / 32, NX / 32),     dim3(32, 8)>>>(c_proj_w, wt2, NX, NX);

    const int gsm_bytes = 4 * 128 * GLD * (int)sizeof(float);   // 73728
    cudaFuncSetAttribute(gemm_mma, cudaFuncAttributeMaxDynamicSharedMemorySize, gsm_bytes);

    // 1) QKV projection
    gemm_mma<<<dim3(3 * NX / 128, M_TOT / 128), 256, gsm_bytes>>>(
        xc, wt1, c_attn_b, qkv, M_TOT, 3 * NX, NX);

    // 1.5) Prep K/V
    prep_kv<<<dim3(S / 64, 64), 256>>>(qkv, kc, vt);

    // 2) Flash attention
    {
        const int smem = (64 * PP + 2 * 64 * KP + 64) * (int)sizeof(float); // 54528
        cudaFuncSetAttribute(flash_attn_mma, cudaFuncAttributeMaxDynamicSharedMemorySize, smem);
        dim3 grid(S / 64, B * H);
        flash_attn_mma<<<grid, 128, smem>>>(qkv, kc, vt, mask, ctx);
    }

    // 3) Output projection
    gemm_mma<<<dim3(NX / 128, M_TOT / 128), 256, gsm_bytes>>>(
        ctx, wt2, c_proj_b, out, M_TOT, NX, NX);
}

// round 10
// speedup vs baseline: 1.2931x; 1.2799x over previous
#include <cuda_runtime.h>
#include <cuda_bf16.h>
#include <math_constants.h>
#include <cstdint>

// Problem constants
#define B   4
#define S   2048
#define NX  1024
#define H   16
#define D   64
#define M_TOT (B * S)   // 8192

// Scratch
__device__ float g_qkv[(size_t)M_TOT * 3 * NX];   // (8192, 3072)
__device__ float g_ctx[(size_t)M_TOT * NX];       // (8192, 1024) tf32-rounded
__device__ float g_xc[(size_t)M_TOT * NX];        // x, tf32-rounded
__device__ float g_wt1[(size_t)3 * NX * NX];      // c_attn_w^T, tf32
__device__ float g_wt2[(size_t)NX * NX];          // c_proj_w^T, tf32
__device__ float g_kc[(size_t)64 * S * D];        // K tf32, [bh][s][d-pperm]
__device__ float g_vt[(size_t)64 * D * S];        // V tf32, [bh][d][s] (no perm)

// ---------------------------------------------------------------------------
// Helpers
// ---------------------------------------------------------------------------
__device__ __forceinline__ uint32_t f2tf32(float x) {
    uint32_t u;
    asm("cvt.rna.tf32.f32 %0, %1;" : "=r"(u) : "f"(x));
    return u;
}
__device__ __forceinline__ float f2tf32f(float x) {
    return __uint_as_float(f2tf32(x));
}

// mma.sync m16n8k8 tf32: D = A*B + D (fp32 accum)
__device__ __forceinline__ void mma8(float* c, const uint32_t* a,
                                     uint32_t b0, uint32_t b1) {
    asm volatile(
        "mma.sync.aligned.m16n8k8.row.col.f32.tf32.tf32.f32 "
        "{%0,%1,%2,%3}, {%4,%5,%6,%7}, {%8,%9}, {%0,%1,%2,%3};"
        : "+f"(c[0]), "+f"(c[1]), "+f"(c[2]), "+f"(c[3])
        : "r"(a[0]), "r"(a[1]), "r"(a[2]), "r"(a[3]), "r"(b0), "r"(b1));
}

// ---------------------------------------------------------------------------
// tf32-convert x
// ---------------------------------------------------------------------------
__global__ void cvt_tf32(const float* __restrict__ in, float* __restrict__ out)
{
    const int i = blockIdx.x * 256 + threadIdx.x;
    float4 v = *(const float4*)(in + (size_t)i * 4);
    v.x = f2tf32f(v.x); v.y = f2tf32f(v.y);
    v.z = f2tf32f(v.z); v.w = f2tf32f(v.w);
    *(float4*)(out + (size_t)i * 4) = v;
}

// ---------------------------------------------------------------------------
// Weight transpose + tf32 convert: Wt[n][k] = tf32(W[k][n])
// ---------------------------------------------------------------------------
__global__ void transpose_cvt(const float* __restrict__ W, float* __restrict__ Wt,
                              int K, int N)
{
    __shared__ float t[32][33];
    const int k0 = blockIdx.y * 32, n0 = blockIdx.x * 32;
    const int x = threadIdx.x, y = threadIdx.y;   // 32 x 8
#pragma unroll
    for (int i = 0; i < 32; i += 8)
        t[y + i][x] = W[(size_t)(k0 + y + i) * N + n0 + x];
    __syncthreads();
#pragma unroll
    for (int i = 0; i < 32; i += 8)
        Wt[(size_t)(n0 + y + i) * K + k0 + x] = f2tf32f(t[x][y + i]);
}

// ---------------------------------------------------------------------------
// Prep K/V: tf32; K d-axis pair-permuted (for QK B-frags); V transposed,
// key axis UNPERMUTED (PV A-frags come straight from score registers).
// ---------------------------------------------------------------------------
__global__ __launch_bounds__(256)
void prep_kv(const float* __restrict__ qkv, float* __restrict__ kc,
             float* __restrict__ vt)
{
    __shared__ float vs[64][65];
    const int bh = blockIdx.y;
    const int b = bh >> 4, h = bh & 15;
    const int s0 = blockIdx.x * 64;
    const int tid = threadIdx.x;

    const float* kbase = qkv + (size_t)b * S * (3 * NX) + NX + h * D;
    const float* vbase = qkv + (size_t)b * S * (3 * NX) + 2 * NX + h * D;

    for (int idx = tid; idx < 64 * 16; idx += 256) {
        const int r  = idx >> 4;
        const int ve = idx & 15;
        const size_t grow = (size_t)(s0 + r) * (3 * NX) + ve * 4;
        float4 kv = *(const float4*)(kbase + grow);
        float* out = kc + ((size_t)bh * S + s0 + r) * D + (ve >> 1) * 8 + (ve & 1);
        out[0] = f2tf32f(kv.x);
        out[2] = f2tf32f(kv.y);
        out[4] = f2tf32f(kv.z);
        out[6] = f2tf32f(kv.w);
        float4 vv = *(const float4*)(vbase + grow);
        vs[4 * ve + 0][r] = vv.x;
        vs[4 * ve + 1][r] = vv.y;
        vs[4 * ve + 2][r] = vv.z;
        vs[4 * ve + 3][r] = vv.w;
    }
    __syncthreads();

    for (int idx = tid; idx < 64 * 16; idx += 256) {
        const int d  = idx >> 4;
        const int ve = idx & 15;
        const int pb = ve * 4;
        float4 ov;
        ov.x = f2tf32f(vs[d][pb + 0]);
        ov.y = f2tf32f(vs[d][pb + 1]);
        ov.z = f2tf32f(vs[d][pb + 2]);
        ov.w = f2tf32f(vs[d][pb + 3]);
        *(float4*)(vt + ((size_t)bh * D + d) * S + s0 + pb) = ov;
    }
}

// ---------------------------------------------------------------------------
// tf32 mma GEMM (round-7 proven version, A pre-converted):
// C[M,N] = A[M,K] @ Bt[N,K]^T + bias[N]
// Block 128x128, K-tile 32, 256 threads = 8 warps; warp tile 64x32.
// ---------------------------------------------------------------------------
#define GLD 36

__global__ __launch_bounds__(256)
void gemm_mma(const float* __restrict__ A, const float* __restrict__ Bt,
              const float* __restrict__ bias, float* __restrict__ C,
              int M, int N, int K)
{
    __shared__ float As[128][GLD];
    __shared__ float Bs[128][GLD];

    const int tid  = threadIdx.x;
    const int wid  = tid >> 5;
    const int lane = tid & 31;
    const int g    = lane >> 2;
    const int tig  = lane & 3;

    const int brow = blockIdx.y * 128;
    const int bcol = blockIdx.x * 128;
    const int wm = (wid >> 2) * 64;
    const int wn = (wid & 3) * 32;

    float c[4][4][4];
#pragma unroll
    for (int mi = 0; mi < 4; mi++)
#pragma unroll
        for (int ni = 0; ni < 4; ni++)
#pragma unroll
            for (int j = 0; j < 4; j++) c[mi][ni][j] = 0.f;

    for (int k0 = 0; k0 < K; k0 += 32) {
        __syncthreads();
#pragma unroll
        for (int i = 0; i < 4; i++) {
            const int v = tid + i * 256;
            const int r  = v >> 3;
            const int ve = v & 7;
            float4 av = *(const float4*)(A + (size_t)(brow + r) * K + k0 + ve * 4);
            *(float4*)&As[r][ve * 4] = av;
            float4 bv = *(const float4*)(Bt + (size_t)(bcol + r) * K + k0 + ve * 4);
            *(float4*)&Bs[r][ve * 4] = bv;
        }
        __syncthreads();

#pragma unroll
        for (int ks = 0; ks < 4; ks++) {
            const int kk = ks * 8;
            uint32_t af[4][4], bf[4][2];
#pragma unroll
            for (int mi = 0; mi < 4; mi++) {
                const int r = wm + mi * 16;
                af[mi][0] = __float_as_uint(As[r + g][kk + tig]);
                af[mi][1] = __float_as_uint(As[r + g + 8][kk + tig]);
                af[mi][2] = __float_as_uint(As[r + g][kk + tig + 4]);
                af[mi][3] = __float_as_uint(As[r + g + 8][kk + tig + 4]);
            }
#pragma unroll
            for (int ni = 0; ni < 4; ni++) {
                const int r = wn + ni * 8;
                bf[ni][0] = __float_as_uint(Bs[r + g][kk + tig]);
                bf[ni][1] = __float_as_uint(Bs[r + g][kk + tig + 4]);
            }
#pragma unroll
            for (int mi = 0; mi < 4; mi++)
#pragma unroll
                for (int ni = 0; ni < 4; ni++)
                    mma8(c[mi][ni], af[mi], bf[ni][0], bf[ni][1]);
        }
    }

#pragma unroll
    for (int mi = 0; mi < 4; mi++) {
        const int row0 = brow + wm + mi * 16 + g;
#pragma unroll
        for (int ni = 0; ni < 4; ni++) {
            const int col = bcol + wn + ni * 8 + 2 * tig;
            float2 bb = *(const float2*)(bias + col);
            float2 v0, v1;
            v0.x = c[mi][ni][0] + bb.x; v0.y = c[mi][ni][1] + bb.y;
            v1.x = c[mi][ni][2] + bb.x; v1.y = c[mi][ni][3] + bb.y;
            *(float2*)(C + (size_t)row0 * N + col) = v0;
            *(float2*)(C + (size_t)(row0 + 8) * N + col) = v1;
        }
    }
}

// ---------------------------------------------------------------------------
// Flash attention: 4 warps, TQ=64, TK=64, 4 CTAs/SM.
// Copy-only staging of K/V. PV A-fragments come DIRECTLY from the QK score
// registers (af = {c0, c2, c1, c3}, tf32-rounded) — no P smem round-trip.
// V keys unpermuted; B-frag float2 reads at cols (2tig, 2tig+1) supply
// logical keys (2tig, 2tig+1) at k-slots (tig, tig+4), matching the A-side.
// ---------------------------------------------------------------------------
#define KP 72
#define PP 68

__global__ void __launch_bounds__(128, 4)
flash_attn_mma(const float* __restrict__ qkv, const float* __restrict__ kc,
               const float* __restrict__ vt, const float* __restrict__ mask,
               float* __restrict__ ctx)
{
    extern __shared__ float sm[];
    float* Qs = sm;                    // [64][PP]  Q staging only
    float* Ks = Qs + 64 * PP;          // [64][KP]  (key, d-pperm)
    float* Vt = Ks + 64 * KP;          // [64][KP]  (d, key)
    float* mk = Vt + 64 * KP;          // [64]

    const int bh = blockIdx.y;
    const int b  = bh >> 4;
    const int h  = bh & 15;
    const int q0 = blockIdx.x * 64;

    const int tid  = threadIdx.x;
    const int wid  = tid >> 5;
    const int lane = tid & 31;
    const int g    = lane >> 2;
    const int tig  = lane & 3;
    const int m0   = wid * 16;

    const float* qptr = qkv + (size_t)b * S * (3 * NX) + (size_t)h * D;
    for (int idx = tid; idx < 64 * 16; idx += 128) {
        const int r  = idx >> 4;
        const int ve = idx & 15;
        float4 qa = *(const float4*)(qptr + (size_t)(q0 + r) * (3 * NX) + ve * 4);
        float* dst = &Qs[r * PP + ve * 4];
        dst[0] = f2tf32f(qa.x);
        dst[1] = f2tf32f(qa.y);
        dst[2] = f2tf32f(qa.z);
        dst[3] = f2tf32f(qa.w);
    }
    __syncthreads();

    uint32_t aq[8][4];
#pragma unroll
    for (int ks = 0; ks < 8; ks++) {
        const int kk = ks * 8;
        aq[ks][0] = __float_as_uint(Qs[(m0 + g) * PP + kk + tig]);
        aq[ks][1] = __float_as_uint(Qs[(m0 + g + 8) * PP + kk + tig]);
        aq[ks][2] = __float_as_uint(Qs[(m0 + g) * PP + kk + tig + 4]);
        aq[ks][3] = __float_as_uint(Qs[(m0 + g + 8) * PP + kk + tig + 4]);
    }

    float mi0 = -CUDART_INF_F, mi1 = -CUDART_INF_F;
    float li0 = 0.f, li1 = 0.f;
    float o[8][4];
#pragma unroll
    for (int ni = 0; ni < 8; ni++)
#pragma unroll
        for (int j = 0; j < 4; j++) o[ni][j] = 0.f;

    const float* kcb = kc + (size_t)bh * S * D;
    const float* vtb = vt + (size_t)bh * D * S;

    for (int kt = 0; kt < S / 64; kt++) {
        const int k0g = kt * 64;
        __syncthreads();

        for (int idx = tid; idx < 64 * 16; idx += 128) {
            const int r  = idx >> 4;
            const int ve = idx & 15;
            float4 kv = *(const float4*)(kcb + (size_t)(k0g + r) * D + ve * 4);
            *(float4*)&Ks[r * KP + ve * 4] = kv;
            float4 vv = *(const float4*)(vtb + (size_t)r * S + k0g + ve * 4);
            *(float4*)&Vt[r * KP + ve * 4] = vv;
        }
        if (tid < 16)
            *(float4*)&mk[tid * 4] = *(const float4*)&mask[(size_t)b * S + k0g + tid * 4];
        __syncthreads();

        // ---- QK^T
        float c[8][4];
#pragma unroll
        for (int ni = 0; ni < 8; ni++)
#pragma unroll
            for (int j = 0; j < 4; j++) c[ni][j] = 0.f;

#pragma unroll
        for (int ks = 0; ks < 8; ks++) {
            const int kk = ks * 8 + 2 * tig;
            uint32_t bf[8][2];
#pragma unroll
            for (int ni = 0; ni < 8; ni++) {
                float2 bb = *(const float2*)&Ks[(ni * 8 + g) * KP + kk];
                bf[ni][0] = __float_as_uint(bb.x);
                bf[ni][1] = __float_as_uint(bb.y);
            }
#pragma unroll
            for (int ni = 0; ni < 8; ni++)
                mma8(c[ni], aq[ks], bf[ni][0], bf[ni][1]);
        }

        // ---- scale + mask
#pragma unroll
        for (int ni = 0; ni < 8; ni++) {
            float2 mm = *(const float2*)&mk[ni * 8 + 2 * tig];
            c[ni][0] = fmaf(c[ni][0], 0.125f, mm.x);
            c[ni][1] = fmaf(c[ni][1], 0.125f, mm.y);
            c[ni][2] = fmaf(c[ni][2], 0.125f, mm.x);
            c[ni][3] = fmaf(c[ni][3], 0.125f, mm.y);
        }

        // ---- online softmax
        float mt0 = -CUDART_INF_F, mt1 = -CUDART_INF_F;
#pragma unroll
        for (int ni = 0; ni < 8; ni++) {
            mt0 = fmaxf(mt0, fmaxf(c[ni][0], c[ni][1]));
            mt1 = fmaxf(mt1, fmaxf(c[ni][2], c[ni][3]));
        }
        mt0 = fmaxf(mt0, __shfl_xor_sync(0xffffffffu, mt0, 1));
        mt0 = fmaxf(mt0, __shfl_xor_sync(0xffffffffu, mt0, 2));
        mt1 = fmaxf(mt1, __shfl_xor_sync(0xffffffffu, mt1, 1));
        mt1 = fmaxf(mt1, __shfl_xor_sync(0xffffffffu, mt1, 2));

        const float mn0 = fmaxf(mi0, mt0);
        const float mn1 = fmaxf(mi1, mt1);
        const float fac0 = __expf(mi0 - mn0);
        const float fac1 = __expf(mi1 - mn1);
        mi0 = mn0; mi1 = mn1;

        float lt0 = 0.f, lt1 = 0.f;
#pragma unroll
        for (int ni = 0; ni < 8; ni++) {
            c[ni][0] = __expf(c[ni][0] - mn0);
            c[ni][1] = __expf(c[ni][1] - mn0);
            c[ni][2] = __expf(c[ni][2] - mn1);
            c[ni][3] = __expf(c[ni][3] - mn1);
            lt0 += c[ni][0] + c[ni][1];
            lt1 += c[ni][2] + c[ni][3];
        }
        lt0 += __shfl_xor_sync(0xffffffffu, lt0, 1);
        lt0 += __shfl_xor_sync(0xffffffffu, lt0, 2);
        lt1 += __shfl_xor_sync(0xffffffffu, lt1, 1);
        lt1 += __shfl_xor_sync(0xffffffffu, lt1, 2);
        li0 = li0 * fac0 + lt0;
        li1 = li1 * fac1 + lt1;

#pragma unroll
        for (int ni = 0; ni < 8; ni++) {
            o[ni][0] *= fac0; o[ni][1] *= fac0;
            o[ni][2] *= fac1; o[ni][3] *= fac1;
        }

        // ---- O += P @ V : A-frags directly from score registers
#pragma unroll
        for (int ks = 0; ks < 8; ks++) {
            uint32_t af[4];
            af[0] = f2tf32(c[ks][0]);   // row g,   key 2tig   -> k-slot tig
            af[1] = f2tf32(c[ks][2]);   // row g+8, key 2tig
            af[2] = f2tf32(c[ks][1]);   // row g,   key 2tig+1 -> k-slot tig+4
            af[3] = f2tf32(c[ks][3]);   // row g+8, key 2tig+1
            const int kkp = ks * 8 + 2 * tig;
            uint32_t bf[8][2];
#pragma unroll
            for (int ni = 0; ni < 8; ni++) {
                float2 bb = *(const float2*)&Vt[(ni * 8 + g) * KP + kkp];
                bf[ni][0] = __float_as_uint(bb.x);
                bf[ni][1] = __float_as_uint(bb.y);
            }
#pragma unroll
            for (int ni = 0; ni < 8; ni++)
                mma8(o[ni], af, bf[ni][0], bf[ni][1]);
        }
    }

    // ---- normalize + write merged-heads context (tf32-rounded)
    const float inv0 = 1.f / li0;
    const float inv1 = 1.f / li1;
    const size_t row0 = (size_t)b * S + q0 + m0 + g;
#pragma unroll
    for (int ni = 0; ni < 8; ni++) {
        const int col = h * D + ni * 8 + 2 * tig;
        float2 v0, v1;
        v0.x = f2tf32f(o[ni][0] * inv0); v0.y = f2tf32f(o[ni][1] * inv0);
        v1.x = f2tf32f(o[ni][2] * inv1); v1.y = f2tf32f(o[ni][3] * inv1);
        *(float2*)(ctx + row0 * NX + col)       = v0;
        *(float2*)(ctx + (row0 + 8) * NX + col) = v1;
    }
}

// ---------------------------------------------------------------------------
// Launch
// ---------------------------------------------------------------------------
extern "C" void kernel_launch(void* const* d_in, const int* in_sizes, int n_in,
                              void* d_out, int out_size)
{
    const float* x        = (const float*)d_in[0];
    const float* mask     = (const float*)d_in[1];
    const float* c_attn_w = (const float*)d_in[2];
    const float* c_attn_b = (const float*)d_in[3];
    const float* c_proj_w = (const float*)d_in[4];
    const float* c_proj_b = (const float*)d_in[5];
    float* out = (float*)d_out;

    float *qkv, *ctx, *xc, *wt1, *wt2, *kc, *vt;
    cudaGetSymbolAddress((void**)&qkv, g_qkv);
    cudaGetSymbolAddress((void**)&ctx, g_ctx);
    cudaGetSymbolAddress((void**)&xc,  g_xc);
    cudaGetSymbolAddress((void**)&wt1, g_wt1);
    cudaGetSymbolAddress((void**)&wt2, g_wt2);
    cudaGetSymbolAddress((void**)&kc,  g_kc);
    cudaGetSymbolAddress((void**)&vt,  g_vt);

    // 0) Pre-convert / pre-transpose
    cvt_tf32<<<M_TOT * NX / (256 * 4), 256>>>(x, xc);
    transpose_cvt<<<dim3(3 * NX / 32, NX / 32), dim3(32, 8)>>>(c_attn_w, wt1, NX, 3 * NX);
    transpose_cvt<<<dim3(NX / 32, NX / 32),     dim3(32, 8)>>>(c_proj_w, wt2, NX, NX);

    // 1) QKV projection
    gemm_mma<<<dim3(3 * NX / 128, M_TOT / 128), 256>>>(xc, wt1, c_attn_b, qkv,
                                                       M_TOT, 3 * NX, NX);

    // 1.5) Prep K/V
    prep_kv<<<dim3(S / 64, 64), 256>>>(qkv, kc, vt);

    // 2) Flash attention (register-resident P)
    {
        const int smem = (64 * PP + 2 * 64 * KP + 64) * (int)sizeof(float); // 54528
        cudaFuncSetAttribute(flash_attn_mma, cudaFuncAttributeMaxDynamicSharedMemorySize, smem);
        dim3 grid(S / 64, B * H);
        flash_attn_mma<<<grid, 128, smem>>>(qkv, kc, vt, mask, ctx);
    }

    // 3) Output projection
    gemm_mma<<<dim3(NX / 128, M_TOT / 128), 256>>>(ctx, wt2, c_proj_b, out,
                                                   M_TOT, NX, NX);
}